// round 8
// baseline (speedup 1.0000x reference)
#include <cuda_runtime.h>
#include <cstdint>
#include <climits>

#define T_STEPS 200
#define B_SZ    256
#define IN_SZ   784
#define N_SZ    400

#define ALPHA      0.9f
#define BETA       0.8f
#define THRESH     1.0f
#define BETA_PLUS  0.9f
#define BETA_MINUS 0.9f
#define A_PLUS     1e-3f
#define A_MINUS    1e-3f
#define LI_STR     0.1f

// ---------------- persistent device state ----------------
__device__ float g_Wt[IN_SZ * N_SZ];       // W transposed: Wt[k*N + n] = W[n, k]
__device__ float g_syn[B_SZ * N_SZ];       // stored PRE-lateral-inhibition (LI applied lazily)
__device__ float g_mem[B_SZ * N_SZ];
__device__ float g_post[B_SZ * N_SZ];
__device__ float g_trT[IN_SZ * B_SZ];      // TRANSPOSED pre-trace: trT[k*B + b] = tr_t[b,k]
__device__ int   g_win[B_SZ];
__device__ int   g_flag[T_STEPS];
__device__ int   g_imgcnt[IN_SZ];
__device__ __align__(16) int g_imglist[IN_SZ * B_SZ]; // per input k: batch rows with img=1
__device__ __align__(16) unsigned g_spkmask[N_SZ * 8]; // per neuron n: 256-bit spike mask over b

// ---------------- init ----------------
__global__ void k_init(const float* __restrict__ W) {
    int idx = blockIdx.x * blockDim.x + threadIdx.x;
    int stride = gridDim.x * blockDim.x;
    for (int j = idx; j < IN_SZ * N_SZ; j += stride) {
        int k = j / N_SZ, n = j % N_SZ;
        g_Wt[j] = W[n * IN_SZ + k];
    }
    for (int j = idx; j < B_SZ * N_SZ; j += stride) {
        g_syn[j] = 0.f; g_mem[j] = 0.f; g_post[j] = 0.f;
    }
    for (int j = idx; j < IN_SZ * B_SZ; j += stride) g_trT[j] = 0.f;
    for (int j = idx; j < T_STEPS; j += stride) g_flag[j] = 0;
}

// ---------------- K1: neuron update (one block per batch row) ----------------
// Fuses: lazy lateral inhibition from step t-1, neuron dynamics, records,
// post-trace update, winner/flag computation.
__global__ void __launch_bounds__(512) k_neuron(const float* __restrict__ img, int t,
                                                float* __restrict__ memrec,
                                                float* __restrict__ spkrec) {
    int b = blockIdx.x;
    int tid = threadIdx.x;
    int w = tid >> 5, lane = tid & 31;

    __shared__ unsigned s_mask[25];   // active-input bitmask over k (25 x 32 >= 784)
    __shared__ int s_win;
    __shared__ int s_any;

    const float* imgt = img + ((size_t)t * B_SZ + b) * IN_SZ;

    // each warp ballots the values it loads: warp w covers chunks w and 16+w
    float v0 = imgt[tid];                                  // k = tid (< 512)
    float v1 = (tid + 512 < IN_SZ) ? imgt[tid + 512] : 0.f; // k = tid+512
    unsigned m0 = __ballot_sync(0xffffffffu, v0 != 0.f);
    unsigned m1 = __ballot_sync(0xffffffffu, v1 != 0.f);
    if (lane == 0) {
        s_mask[w] = m0;
        if (w < 9) s_mask[16 + w] = m1;
    }
    if (tid == 0) { s_win = INT_MAX; s_any = 0; }

    // lazy LI inputs from previous step (finished launches -> coherent)
    int winp  = g_win[b];
    int flagp = (t > 0) ? g_flag[t - 1] : 0;
    __syncthreads();

    if (tid < N_SZ) {
        int n = tid;
        float c0 = 0.f, c1 = 0.f;
#pragma unroll
        for (int c = 0; c < 25; c++) {
            unsigned m = s_mask[c];
            const float* base = g_Wt + c * 32 * N_SZ + n;
            while (m) {
                int bit = __ffs(m) - 1;
                m &= m - 1;
                if (c & 1) c1 += base[bit * N_SZ];
                else       c0 += base[bit * N_SZ];
            }
        }
        float cur = c0 + c1;

        float mv = g_mem[b * N_SZ + n];
        float s  = g_syn[b * N_SZ + n];
        if (flagp && n != winp) s -= LI_STR;         // lazy lateral inhibition
        float reset = (mv > THRESH) ? 1.0f : 0.0f;
        s  = ALPHA * s + cur;
        mv = BETA * mv + s - reset * THRESH;
        float spk = (mv > THRESH) ? 1.0f : 0.0f;

        size_t rec = ((size_t)t * B_SZ + b) * N_SZ + n;
        memrec[rec] = mv;
        spkrec[rec] = spk;
        g_syn[b * N_SZ + n] = s;                     // pre-LI; LI applied next step
        g_mem[b * N_SZ + n] = mv;
        g_post[b * N_SZ + n] = BETA_MINUS * g_post[b * N_SZ + n] + spk;

        if (spk != 0.f) { atomicMin(&s_win, n); s_any = 1; }
    }
    __syncthreads();
    if (tid == 0) {
        g_win[b] = (s_win == INT_MAX) ? 0 : s_win;
        if (s_any) atomicOr(&g_flag[t], 1);
    }
}

// ---------------- K2: prep ----------------
// Blocks [0,98):    img-active lists per k (8 warps x 98 = 784)
// Blocks [98,148):  spike bitmasks per n (8 warps x 50 = 400)
// Blocks [148,348): transposed trace update trT = bp*trT + img[t-1]^T (32x32 tiles)
#define PREP_IMG  98
#define PREP_MSK  148
#define PREP_TOT  348
__global__ void __launch_bounds__(256) k_prep(const float* __restrict__ img,
                                              const float* __restrict__ spkrec, int t) {
    int bid = blockIdx.x;
    int tid = threadIdx.x;

    if (bid < PREP_IMG) {
        int w = tid >> 5, lane = tid & 31;
        int k = bid * 8 + w;
        const float* imgt = img + (size_t)t * B_SZ * IN_SZ;
        int base = 0;
        for (int c = 0; c < B_SZ / 32; c++) {
            int b = c * 32 + lane;
            bool a = imgt[(size_t)b * IN_SZ + k] != 0.0f;
            unsigned m = __ballot_sync(0xffffffffu, a);
            if (a) g_imglist[k * B_SZ + base + __popc(m & ((1u << lane) - 1u))] = b;
            base += __popc(m);
        }
        if (lane == 0) g_imgcnt[k] = base;
    } else if (bid < PREP_MSK) {
        int w = tid >> 5, lane = tid & 31;
        int n = (bid - PREP_IMG) * 8 + w;
        const float* spkt = spkrec + (size_t)t * B_SZ * N_SZ;
        for (int c = 0; c < B_SZ / 32; c++) {
            int b = c * 32 + lane;
            bool a = spkt[b * N_SZ + n] != 0.0f;
            unsigned m = __ballot_sync(0xffffffffu, a);
            if (lane == 0) g_spkmask[n * 8 + c] = m;
        }
    } else {
        if (t == 0) return;   // trT stays zero for step 0
        int d = bid - PREP_MSK;            // 0..199
        int kt = d % 25, bt = d / 25;      // 25 k-tiles x 8 b-tiles
        int k0 = kt * 32, b0 = bt * 32;
        __shared__ float s[32][33];
        int tx = tid & 31, ty = tid >> 5;  // ty 0..7
        const float* imgp = img + (size_t)(t - 1) * B_SZ * IN_SZ;
#pragma unroll
        for (int r = 0; r < 4; r++) {
            int bl = ty + r * 8;           // local b
            int k = k0 + tx;
            s[bl][tx] = (k < IN_SZ) ? imgp[(size_t)(b0 + bl) * IN_SZ + k] : 0.f;
        }
        __syncthreads();
#pragma unroll
        for (int r = 0; r < 4; r++) {
            int kl = ty + r * 8;           // local k
            int k = k0 + kl;
            if (k < IN_SZ) {
                int j = k * B_SZ + b0 + tx;
                g_trT[j] = BETA_PLUS * g_trT[j] + s[tx][kl];
            }
        }
    }
}

// ---------------- K3: fused STDP update, one block per input k ----------------
// Wt[k,n] = clip(Wt[k,n] + A_PLUS * sum_{b: spk[b,n]=1} trT[k,b]
//                        - A_MINUS * sum_{b: img[b,k]=1} post[b,n], 0, 1)
__global__ void __launch_bounds__(416) k_stdp() {
    int k = blockIdx.x;
    int tid = threadIdx.x;

    __shared__ float s_tr[B_SZ];
    __shared__ float s_ps[8];      // per-32-chunk partial sums of s_tr

    // issue all independent loads up front
    uint4 mA = make_uint4(0, 0, 0, 0), mB = make_uint4(0, 0, 0, 0);
    float wv = 0.f;
    if (tid < N_SZ) {
        const uint4* mp = reinterpret_cast<const uint4*>(&g_spkmask[tid * 8]);
        mA = mp[0]; mB = mp[1];
        wv = g_Wt[k * N_SZ + tid];
    }
    int icnt = g_imgcnt[k];        // warp-uniform broadcast load, no barrier needed

    float trv = 0.f;
    if (tid < B_SZ) {
        trv = g_trT[k * B_SZ + tid];
        s_tr[tid] = trv;
        // deterministic per-chunk reduction (fixed shfl tree)
        float v = trv;
#pragma unroll
        for (int off = 16; off > 0; off >>= 1)
            v += __shfl_xor_sync(0xffffffffu, v, off);
        if ((tid & 31) == 0) s_ps[tid >> 5] = v;
    }
    __syncthreads();

    int n = tid;
    if (n < N_SZ) {
        // LTP via spike bitmask over smem trace row (complement trick caps work at 16 bits/word)
        unsigned mw[8] = {mA.x, mA.y, mA.z, mA.w, mB.x, mB.y, mB.z, mB.w};
        float ltp = 0.f;
#pragma unroll
        for (int w = 0; w < 8; w++) {
            unsigned m = mw[w];
            int pc = __popc(m);
            const float* base = s_tr + w * 32;
            if (pc == 32) {
                ltp += s_ps[w];
            } else if (pc > 16) {
                unsigned c = ~m;
                float neg = 0.f;
                do {
                    int b = __ffs(c) - 1;
                    c &= c - 1;
                    neg += base[b];
                } while (c);
                ltp += s_ps[w] - neg;
            } else if (m) {
                do {
                    int b = __ffs(m) - 1;
                    m &= m - 1;
                    ltp += base[b];
                } while (m);
            }
        }

        // LTD via img-active list: int4 index loads + 4 independent accumulators
        const int* lst = &g_imglist[k * B_SZ];
        float d0 = 0.f, d1 = 0.f, d2 = 0.f, d3 = 0.f;
        int i = 0;
        for (; i + 4 <= icnt; i += 4) {
            int4 b4 = *reinterpret_cast<const int4*>(lst + i);
            d0 += g_post[b4.x * N_SZ + n];
            d1 += g_post[b4.y * N_SZ + n];
            d2 += g_post[b4.z * N_SZ + n];
            d3 += g_post[b4.w * N_SZ + n];
        }
        for (; i < icnt; i++) d0 += g_post[lst[i] * N_SZ + n];
        float ltd = (d0 + d1) + (d2 + d3);

        wv = wv + A_PLUS * ltp - A_MINUS * ltd;
        wv = fminf(fmaxf(wv, 0.f), 1.f);
        g_Wt[k * N_SZ + n] = wv;
    }
}

// ---------------- final: transpose Wt back into output layout [N, IN] ----------------
__global__ void k_write_w(float* __restrict__ outW) {
    int idx = blockIdx.x * blockDim.x + threadIdx.x;
    if (idx >= N_SZ * IN_SZ) return;
    int n = idx / IN_SZ, k = idx % IN_SZ;
    outW[idx] = g_Wt[k * N_SZ + n];
}

// ---------------- launch ----------------
extern "C" void kernel_launch(void* const* d_in, const int* in_sizes, int n_in,
                              void* d_out, int out_size) {
    const float* img = (const float*)d_in[0];
    const float* W   = (const float*)d_in[1];
    if (n_in >= 2 && in_sizes[0] == N_SZ * IN_SZ) {
        const float* tmp = img; img = W; W = tmp;
    }

    float* out = (float*)d_out;
    float* memrec = out;
    float* spkrec = out + (size_t)T_STEPS * B_SZ * N_SZ;
    float* outW   = out + 2 * (size_t)T_STEPS * B_SZ * N_SZ;

    k_init<<<256, 256>>>(W);

    for (int t = 0; t < T_STEPS; t++) {
        k_neuron<<<B_SZ, 512>>>(img, t, memrec, spkrec);
        k_prep<<<PREP_TOT, 256>>>(img, spkrec, t);
        k_stdp<<<IN_SZ, 416>>>();
    }
    k_write_w<<<(N_SZ * IN_SZ + 255) / 256, 256>>>(outW);
}

// round 9
// speedup vs baseline: 1.2730x; 1.2730x over previous
#include <cuda_runtime.h>
#include <cstdint>
#include <climits>

#define T_STEPS 200
#define B_SZ    256
#define IN_SZ   784
#define N_SZ    400

#define ALPHA      0.9f
#define BETA       0.8f
#define THRESH     1.0f
#define BETA_PLUS  0.9f
#define BETA_MINUS 0.9f
#define A_PLUS     1e-3f
#define A_MINUS    1e-3f
#define LI_STR     0.1f

// ---------------- persistent device state ----------------
__device__ float g_Wt[IN_SZ * N_SZ];       // W transposed: Wt[k*N + n] = W[n, k]
__device__ float g_syn[B_SZ * N_SZ];
__device__ float g_mem[B_SZ * N_SZ];
__device__ float g_post[B_SZ * N_SZ];
__device__ float g_trT[IN_SZ * B_SZ];      // TRANSPOSED pre-trace: trT[k*B + b] = tr_t[b,k]
__device__ int   g_win[B_SZ];
__device__ int   g_flag[T_STEPS];
__device__ int   g_imgcnt[IN_SZ];
__device__ __align__(16) int g_imglist[IN_SZ * B_SZ];  // per input k: batch rows with img=1
__device__ __align__(16) unsigned g_spkmask[N_SZ * 8]; // per neuron n: 256-bit spike mask over b

// ---------------- init ----------------
__global__ void k_init(const float* __restrict__ W) {
    int idx = blockIdx.x * blockDim.x + threadIdx.x;
    int stride = gridDim.x * blockDim.x;
    for (int j = idx; j < IN_SZ * N_SZ; j += stride) {
        int k = j / N_SZ, n = j % N_SZ;
        g_Wt[j] = W[n * IN_SZ + k];
    }
    for (int j = idx; j < B_SZ * N_SZ; j += stride) {
        g_syn[j] = 0.f; g_mem[j] = 0.f; g_post[j] = 0.f;
    }
    for (int j = idx; j < IN_SZ * B_SZ; j += stride) g_trT[j] = 0.f;
    for (int j = idx; j < T_STEPS; j += stride) g_flag[j] = 0;
}

// ---------------- K1: neuron update (one block per batch row) ----------------
__global__ void __launch_bounds__(512) k_neuron(const float* __restrict__ img, int t,
                                                float* __restrict__ memrec,
                                                float* __restrict__ spkrec) {
    int b = blockIdx.x;
    int tid = threadIdx.x;

    __shared__ float simg[IN_SZ];
    __shared__ int   s_act[IN_SZ];
    __shared__ int   s_cnt;
    __shared__ int   s_win;
    __shared__ int   s_any;

    const float* imgt = img + ((size_t)t * B_SZ + b) * IN_SZ;
    for (int k = tid; k < IN_SZ; k += 512) simg[k] = imgt[k];
    if (tid == 0) { s_win = INT_MAX; s_any = 0; }
    __syncthreads();

    // warp 0: order-preserving compaction of active input indices
    if (tid < 32) {
        int base = 0;
        for (int c = 0; c < (IN_SZ + 31) / 32; c++) {
            int k = c * 32 + tid;
            bool act = (k < IN_SZ) && (simg[k] != 0.0f);
            unsigned m = __ballot_sync(0xffffffffu, act);
            if (act) s_act[base + __popc(m & ((1u << tid) - 1u))] = k;
            base += __popc(m);
        }
        if (tid == 0) s_cnt = base;
    }
    __syncthreads();

    int cnt = s_cnt;
    if (tid < N_SZ) {
        int n = tid;
        // hoist state loads so they overlap the gather
        float m = g_mem[b * N_SZ + n];
        float s = g_syn[b * N_SZ + n];

        float cur = 0.f;
        for (int i = 0; i < cnt; i++) cur += g_Wt[s_act[i] * N_SZ + n];

        float reset = (m > THRESH) ? 1.0f : 0.0f;
        s = ALPHA * s + cur;
        m = BETA * m + s - reset * THRESH;
        float spk = (m > THRESH) ? 1.0f : 0.0f;

        size_t rec = ((size_t)t * B_SZ + b) * N_SZ + n;
        memrec[rec] = m;
        spkrec[rec] = spk;
        g_syn[b * N_SZ + n] = s;
        g_mem[b * N_SZ + n] = m;

        if (spk != 0.f) { atomicMin(&s_win, n); s_any = 1; }
    }
    __syncthreads();
    if (tid == 0) {
        g_win[b] = (s_win == INT_MAX) ? 0 : s_win;
        if (s_any) atomicOr(&g_flag[t], 1);
    }
}

// ---------------- K2: prep ----------------
// Blocks [0,98):    img-active lists per k (8 warps x 98 = 784)
// Blocks [98,148):  spike bitmasks per n (8 warps x 50 = 400)
// Blocks [148,548): element-wise LI + post-trace update over [B,N]
// Blocks [548,748): transposed trace update trT = bp*trT + img[t-1]^T (32x32 tiles)
#define PREP_IMG  98
#define PREP_MSK  148
#define PREP_LI   548
#define PREP_TOT  748
__global__ void __launch_bounds__(256) k_prep(const float* __restrict__ img,
                                              const float* __restrict__ spkrec, int t) {
    int bid = blockIdx.x;
    int tid = threadIdx.x;

    if (bid < PREP_IMG) {
        int w = tid >> 5, lane = tid & 31;
        int k = bid * 8 + w;
        const float* imgt = img + (size_t)t * B_SZ * IN_SZ;
        int base = 0;
        for (int c = 0; c < B_SZ / 32; c++) {
            int b = c * 32 + lane;
            bool a = imgt[(size_t)b * IN_SZ + k] != 0.0f;
            unsigned m = __ballot_sync(0xffffffffu, a);
            if (a) g_imglist[k * B_SZ + base + __popc(m & ((1u << lane) - 1u))] = b;
            base += __popc(m);
        }
        if (lane == 0) g_imgcnt[k] = base;
    } else if (bid < PREP_MSK) {
        int w = tid >> 5, lane = tid & 31;
        int n = (bid - PREP_IMG) * 8 + w;
        const float* spkt = spkrec + (size_t)t * B_SZ * N_SZ;
        for (int c = 0; c < B_SZ / 32; c++) {
            int b = c * 32 + lane;
            bool a = spkt[b * N_SZ + n] != 0.0f;
            unsigned m = __ballot_sync(0xffffffffu, a);
            if (lane == 0) g_spkmask[n * 8 + c] = m;
        }
    } else if (bid < PREP_LI) {
        int idx = (bid - PREP_MSK) * 256 + tid;
        if (idx < B_SZ * N_SZ) {
            int b = idx / N_SZ, n = idx % N_SZ;
            float spk = spkrec[(size_t)t * B_SZ * N_SZ + idx];
            if (g_flag[t]) {
                if (n != g_win[b]) g_syn[idx] -= LI_STR;
            }
            g_post[idx] = BETA_MINUS * g_post[idx] + spk;
        }
    } else {
        if (t == 0) return;   // trT stays zero for step 0
        int d = bid - PREP_LI;             // 0..199
        int kt = d % 25, bt = d / 25;      // 25 k-tiles x 8 b-tiles
        int k0 = kt * 32, b0 = bt * 32;
        __shared__ float s[32][33];
        int tx = tid & 31, ty = tid >> 5;  // ty 0..7
        const float* imgp = img + (size_t)(t - 1) * B_SZ * IN_SZ;
#pragma unroll
        for (int r = 0; r < 4; r++) {
            int bl = ty + r * 8;           // local b
            int k = k0 + tx;
            s[bl][tx] = (k < IN_SZ) ? imgp[(size_t)(b0 + bl) * IN_SZ + k] : 0.f;
        }
        __syncthreads();
#pragma unroll
        for (int r = 0; r < 4; r++) {
            int kl = ty + r * 8;           // local k
            int k = k0 + kl;
            if (k < IN_SZ) {
                int j = k * B_SZ + b0 + tx;
                g_trT[j] = BETA_PLUS * g_trT[j] + s[tx][kl];
            }
        }
    }
}

// ---------------- K3: fused STDP update, one block per input k ----------------
// Wt[k,n] = clip(Wt[k,n] + A_PLUS * sum_{b: spk[b,n]=1} trT[k,b]
//                        - A_MINUS * sum_{b: img[b,k]=1} post[b,n], 0, 1)
__global__ void __launch_bounds__(416) k_stdp() {
    int k = blockIdx.x;
    int tid = threadIdx.x;

    __shared__ float s_tr[B_SZ];
    __shared__ float s_ps[8];      // per-32-chunk partial sums of s_tr

    // issue all independent loads up front
    uint4 mA = make_uint4(0, 0, 0, 0), mB = make_uint4(0, 0, 0, 0);
    float wv = 0.f;
    if (tid < N_SZ) {
        const uint4* mp = reinterpret_cast<const uint4*>(&g_spkmask[tid * 8]);
        mA = mp[0]; mB = mp[1];
        wv = g_Wt[k * N_SZ + tid];
    }
    int icnt = g_imgcnt[k];        // warp-uniform broadcast load, no barrier needed

    if (tid < B_SZ) {
        float trv = g_trT[k * B_SZ + tid];
        s_tr[tid] = trv;
        // deterministic per-chunk reduction (fixed shfl tree)
        float v = trv;
#pragma unroll
        for (int off = 16; off > 0; off >>= 1)
            v += __shfl_xor_sync(0xffffffffu, v, off);
        if ((tid & 31) == 0) s_ps[tid >> 5] = v;
    }
    __syncthreads();

    int n = tid;
    if (n < N_SZ) {
        // LTP via spike bitmask over smem trace row (complement trick caps work at 16 bits/word)
        unsigned mw[8] = {mA.x, mA.y, mA.z, mA.w, mB.x, mB.y, mB.z, mB.w};
        float ltp = 0.f;
#pragma unroll
        for (int w = 0; w < 8; w++) {
            unsigned m = mw[w];
            int pc = __popc(m);
            const float* base = s_tr + w * 32;
            if (pc == 32) {
                ltp += s_ps[w];
            } else if (pc > 16) {
                unsigned c = ~m;
                float neg = 0.f;
                do {
                    int b = __ffs(c) - 1;
                    c &= c - 1;
                    neg += base[b];
                } while (c);
                ltp += s_ps[w] - neg;
            } else if (m) {
                do {
                    int b = __ffs(m) - 1;
                    m &= m - 1;
                    ltp += base[b];
                } while (m);
            }
        }

        // LTD via img-active list: int4 index loads + 4 independent accumulators
        const int* lst = &g_imglist[k * B_SZ];
        float d0 = 0.f, d1 = 0.f, d2 = 0.f, d3 = 0.f;
        int i = 0;
        for (; i + 4 <= icnt; i += 4) {
            int4 b4 = *reinterpret_cast<const int4*>(lst + i);
            d0 += g_post[b4.x * N_SZ + n];
            d1 += g_post[b4.y * N_SZ + n];
            d2 += g_post[b4.z * N_SZ + n];
            d3 += g_post[b4.w * N_SZ + n];
        }
        for (; i < icnt; i++) d0 += g_post[lst[i] * N_SZ + n];
        float ltd = (d0 + d1) + (d2 + d3);

        wv = wv + A_PLUS * ltp - A_MINUS * ltd;
        wv = fminf(fmaxf(wv, 0.f), 1.f);
        g_Wt[k * N_SZ + n] = wv;
    }
}

// ---------------- final: transpose Wt back into output layout [N, IN] ----------------
__global__ void k_write_w(float* __restrict__ outW) {
    int idx = blockIdx.x * blockDim.x + threadIdx.x;
    if (idx >= N_SZ * IN_SZ) return;
    int n = idx / IN_SZ, k = idx % IN_SZ;
    outW[idx] = g_Wt[k * N_SZ + n];
}

// ---------------- launch ----------------
extern "C" void kernel_launch(void* const* d_in, const int* in_sizes, int n_in,
                              void* d_out, int out_size) {
    const float* img = (const float*)d_in[0];
    const float* W   = (const float*)d_in[1];
    if (n_in >= 2 && in_sizes[0] == N_SZ * IN_SZ) {
        const float* tmp = img; img = W; W = tmp;
    }

    float* out = (float*)d_out;
    float* memrec = out;
    float* spkrec = out + (size_t)T_STEPS * B_SZ * N_SZ;
    float* outW   = out + 2 * (size_t)T_STEPS * B_SZ * N_SZ;

    k_init<<<256, 256>>>(W);

    for (int t = 0; t < T_STEPS; t++) {
        k_neuron<<<B_SZ, 512>>>(img, t, memrec, spkrec);
        k_prep<<<PREP_TOT, 256>>>(img, spkrec, t);
        k_stdp<<<IN_SZ, 416>>>();
    }
    k_write_w<<<(N_SZ * IN_SZ + 255) / 256, 256>>>(outW);
}

// round 10
// speedup vs baseline: 1.3757x; 1.0807x over previous
#include <cuda_runtime.h>
#include <cstdint>
#include <climits>

#define T_STEPS 200
#define B_SZ    256
#define IN_SZ   784
#define N_SZ    400
#define N_HALF  200

#define ALPHA      0.9f
#define BETA       0.8f
#define THRESH     1.0f
#define BETA_PLUS  0.9f
#define BETA_MINUS 0.9f
#define A_PLUS     1e-3f
#define A_MINUS    1e-3f
#define LI_STR     0.1f

// ---------------- persistent device state ----------------
__device__ float g_Wt[IN_SZ * N_SZ];       // W transposed: Wt[k*N + n] = W[n, k]
__device__ float g_syn[B_SZ * N_SZ];
__device__ float g_mem[B_SZ * N_SZ];
__device__ float g_post[B_SZ * N_SZ];
__device__ float g_trT[IN_SZ * B_SZ];      // TRANSPOSED pre-trace: trT[k*B + b] = tr_t[b,k]
__device__ int   g_win[T_STEPS * B_SZ];    // per (t,b) winner via atomicMin
__device__ int   g_flag[T_STEPS];
__device__ int   g_imgcnt[IN_SZ];
__device__ __align__(16) int g_imglist[IN_SZ * B_SZ];  // per input k: batch rows with img=1
__device__ __align__(16) unsigned g_spkmask[N_SZ * 8]; // per neuron n: 256-bit spike mask over b

// ---------------- init ----------------
__global__ void k_init(const float* __restrict__ W) {
    int idx = blockIdx.x * blockDim.x + threadIdx.x;
    int stride = gridDim.x * blockDim.x;
    for (int j = idx; j < IN_SZ * N_SZ; j += stride) {
        int k = j / N_SZ, n = j % N_SZ;
        g_Wt[j] = W[n * IN_SZ + k];
    }
    for (int j = idx; j < B_SZ * N_SZ; j += stride) {
        g_syn[j] = 0.f; g_mem[j] = 0.f; g_post[j] = 0.f;
    }
    for (int j = idx; j < IN_SZ * B_SZ; j += stride) g_trT[j] = 0.f;
    for (int j = idx; j < T_STEPS * B_SZ; j += stride) g_win[j] = INT_MAX;
    for (int j = idx; j < T_STEPS; j += stride) g_flag[j] = 0;
}

// ---------------- K1: neuron update, grid (B, 2): one block per (batch row, n-half) ----
__global__ void __launch_bounds__(256) k_neuron(const float* __restrict__ img, int t,
                                                float* __restrict__ memrec,
                                                float* __restrict__ spkrec) {
    int b = blockIdx.x;
    int half = blockIdx.y;
    int tid = threadIdx.x;

    __shared__ float simg[IN_SZ];
    __shared__ int   s_act[IN_SZ];
    __shared__ int   s_cnt;
    __shared__ int   s_win;
    __shared__ int   s_any;

    const float* imgt = img + ((size_t)t * B_SZ + b) * IN_SZ;
    for (int k = tid; k < IN_SZ; k += 256) simg[k] = imgt[k];
    if (tid == 0) { s_win = INT_MAX; s_any = 0; }
    __syncthreads();

    // warp 0: order-preserving compaction of active input indices
    if (tid < 32) {
        int base = 0;
        for (int c = 0; c < (IN_SZ + 31) / 32; c++) {
            int k = c * 32 + tid;
            bool act = (k < IN_SZ) && (simg[k] != 0.0f);
            unsigned m = __ballot_sync(0xffffffffu, act);
            if (act) s_act[base + __popc(m & ((1u << tid) - 1u))] = k;
            base += __popc(m);
        }
        if (tid == 0) s_cnt = base;
    }
    __syncthreads();

    int cnt = s_cnt;
    if (tid < N_HALF) {
        int n = half * N_HALF + tid;
        // hoist state loads so they overlap the gather
        float m = g_mem[b * N_SZ + n];
        float s = g_syn[b * N_SZ + n];

        float cur = 0.f;
        for (int i = 0; i < cnt; i++) cur += g_Wt[s_act[i] * N_SZ + n];

        float reset = (m > THRESH) ? 1.0f : 0.0f;
        s = ALPHA * s + cur;
        m = BETA * m + s - reset * THRESH;
        float spk = (m > THRESH) ? 1.0f : 0.0f;

        size_t rec = ((size_t)t * B_SZ + b) * N_SZ + n;
        memrec[rec] = m;
        spkrec[rec] = spk;
        g_syn[b * N_SZ + n] = s;
        g_mem[b * N_SZ + n] = m;

        if (spk != 0.f) { atomicMin(&s_win, n); s_any = 1; }
    }
    __syncthreads();
    if (tid == 0) {
        if (s_win != INT_MAX) atomicMin(&g_win[t * B_SZ + b], s_win);
        if (s_any) atomicOr(&g_flag[t], 1);
    }
}

// ---------------- K2: prep ----------------
// Blocks [0,98):    img-active lists per k (8 warps x 98 = 784)
// Blocks [98,148):  spike bitmasks per n (8 warps x 50 = 400)
// Blocks [148,548): element-wise LI + post-trace update over [B,N]
// Blocks [548,748): transposed trace update trT = bp*trT + img[t-1]^T (32x32 tiles)
#define PREP_IMG  98
#define PREP_MSK  148
#define PREP_LI   548
#define PREP_TOT  748
__global__ void __launch_bounds__(256) k_prep(const float* __restrict__ img,
                                              const float* __restrict__ spkrec, int t) {
    int bid = blockIdx.x;
    int tid = threadIdx.x;

    if (bid < PREP_IMG) {
        int w = tid >> 5, lane = tid & 31;
        int k = bid * 8 + w;
        const float* imgt = img + (size_t)t * B_SZ * IN_SZ;
        int base = 0;
        for (int c = 0; c < B_SZ / 32; c++) {
            int b = c * 32 + lane;
            bool a = imgt[(size_t)b * IN_SZ + k] != 0.0f;
            unsigned m = __ballot_sync(0xffffffffu, a);
            if (a) g_imglist[k * B_SZ + base + __popc(m & ((1u << lane) - 1u))] = b;
            base += __popc(m);
        }
        if (lane == 0) g_imgcnt[k] = base;
    } else if (bid < PREP_MSK) {
        int w = tid >> 5, lane = tid & 31;
        int n = (bid - PREP_IMG) * 8 + w;
        const float* spkt = spkrec + (size_t)t * B_SZ * N_SZ;
        for (int c = 0; c < B_SZ / 32; c++) {
            int b = c * 32 + lane;
            bool a = spkt[b * N_SZ + n] != 0.0f;
            unsigned m = __ballot_sync(0xffffffffu, a);
            if (lane == 0) g_spkmask[n * 8 + c] = m;
        }
    } else if (bid < PREP_LI) {
        int idx = (bid - PREP_MSK) * 256 + tid;
        if (idx < B_SZ * N_SZ) {
            int b = idx / N_SZ, n = idx % N_SZ;
            float spk = spkrec[(size_t)t * B_SZ * N_SZ + idx];
            if (g_flag[t]) {
                int win = g_win[t * B_SZ + b];
                if (win == INT_MAX) win = 0;   // argmax of all-zeros row = 0
                if (n != win) g_syn[idx] -= LI_STR;
            }
            g_post[idx] = BETA_MINUS * g_post[idx] + spk;
        }
    } else {
        if (t == 0) return;   // trT stays zero for step 0
        int d = bid - PREP_LI;             // 0..199
        int kt = d % 25, bt = d / 25;      // 25 k-tiles x 8 b-tiles
        int k0 = kt * 32, b0 = bt * 32;
        __shared__ float s[32][33];
        int tx = tid & 31, ty = tid >> 5;  // ty 0..7
        const float* imgp = img + (size_t)(t - 1) * B_SZ * IN_SZ;
#pragma unroll
        for (int r = 0; r < 4; r++) {
            int bl = ty + r * 8;           // local b
            int k = k0 + tx;
            s[bl][tx] = (k < IN_SZ) ? imgp[(size_t)(b0 + bl) * IN_SZ + k] : 0.f;
        }
        __syncthreads();
#pragma unroll
        for (int r = 0; r < 4; r++) {
            int kl = ty + r * 8;           // local k
            int k = k0 + kl;
            if (k < IN_SZ) {
                int j = k * B_SZ + b0 + tx;
                g_trT[j] = BETA_PLUS * g_trT[j] + s[tx][kl];
            }
        }
    }
}

// ---------------- K3: fused STDP update, grid (IN, 2): one block per (k, n-half) ----
// Wt[k,n] = clip(Wt[k,n] + A_PLUS * sum_{b: spk[b,n]=1} trT[k,b]
//                        - A_MINUS * sum_{b: img[b,k]=1} post[b,n], 0, 1)
__global__ void __launch_bounds__(256) k_stdp() {
    int k = blockIdx.x;
    int half = blockIdx.y;
    int tid = threadIdx.x;
    int n = half * N_HALF + tid;

    __shared__ float s_tr[B_SZ];
    __shared__ float s_ps[8];      // per-32-chunk partial sums of s_tr

    // issue all independent loads up front
    uint4 mA = make_uint4(0, 0, 0, 0), mB = make_uint4(0, 0, 0, 0);
    float wv = 0.f;
    if (tid < N_HALF) {
        const uint4* mp = reinterpret_cast<const uint4*>(&g_spkmask[n * 8]);
        mA = mp[0]; mB = mp[1];
        wv = g_Wt[k * N_SZ + n];
    }
    int icnt = g_imgcnt[k];        // warp-uniform broadcast load, no barrier needed

    // all 8 warps: load trace row + deterministic per-chunk reduction
    {
        float trv = g_trT[k * B_SZ + tid];
        s_tr[tid] = trv;
        float v = trv;
#pragma unroll
        for (int off = 16; off > 0; off >>= 1)
            v += __shfl_xor_sync(0xffffffffu, v, off);
        if ((tid & 31) == 0) s_ps[tid >> 5] = v;
    }
    __syncthreads();

    if (tid < N_HALF) {
        // LTP via spike bitmask over smem trace row (complement trick caps work at 16 bits/word)
        unsigned mw[8] = {mA.x, mA.y, mA.z, mA.w, mB.x, mB.y, mB.z, mB.w};
        float ltp = 0.f;
#pragma unroll
        for (int w = 0; w < 8; w++) {
            unsigned m = mw[w];
            int pc = __popc(m);
            const float* base = s_tr + w * 32;
            if (pc == 32) {
                ltp += s_ps[w];
            } else if (pc > 16) {
                unsigned c = ~m;
                float neg = 0.f;
                do {
                    int b = __ffs(c) - 1;
                    c &= c - 1;
                    neg += base[b];
                } while (c);
                ltp += s_ps[w] - neg;
            } else if (m) {
                do {
                    int b = __ffs(m) - 1;
                    m &= m - 1;
                    ltp += base[b];
                } while (m);
            }
        }

        // LTD via img-active list: int4 index loads + 4 independent accumulators
        const int* lst = &g_imglist[k * B_SZ];
        float d0 = 0.f, d1 = 0.f, d2 = 0.f, d3 = 0.f;
        int i = 0;
        for (; i + 4 <= icnt; i += 4) {
            int4 b4 = *reinterpret_cast<const int4*>(lst + i);
            d0 += g_post[b4.x * N_SZ + n];
            d1 += g_post[b4.y * N_SZ + n];
            d2 += g_post[b4.z * N_SZ + n];
            d3 += g_post[b4.w * N_SZ + n];
        }
        for (; i < icnt; i++) d0 += g_post[lst[i] * N_SZ + n];
        float ltd = (d0 + d1) + (d2 + d3);

        wv = wv + A_PLUS * ltp - A_MINUS * ltd;
        wv = fminf(fmaxf(wv, 0.f), 1.f);
        g_Wt[k * N_SZ + n] = wv;
    }
}

// ---------------- final: transpose Wt back into output layout [N, IN] ----------------
__global__ void k_write_w(float* __restrict__ outW) {
    int idx = blockIdx.x * blockDim.x + threadIdx.x;
    if (idx >= N_SZ * IN_SZ) return;
    int n = idx / IN_SZ, k = idx % IN_SZ;
    outW[idx] = g_Wt[k * N_SZ + n];
}

// ---------------- launch ----------------
extern "C" void kernel_launch(void* const* d_in, const int* in_sizes, int n_in,
                              void* d_out, int out_size) {
    const float* img = (const float*)d_in[0];
    const float* W   = (const float*)d_in[1];
    if (n_in >= 2 && in_sizes[0] == N_SZ * IN_SZ) {
        const float* tmp = img; img = W; W = tmp;
    }

    float* out = (float*)d_out;
    float* memrec = out;
    float* spkrec = out + (size_t)T_STEPS * B_SZ * N_SZ;
    float* outW   = out + 2 * (size_t)T_STEPS * B_SZ * N_SZ;

    k_init<<<256, 256>>>(W);

    dim3 gridN(B_SZ, 2);
    dim3 gridS(IN_SZ, 2);
    for (int t = 0; t < T_STEPS; t++) {
        k_neuron<<<gridN, 256>>>(img, t, memrec, spkrec);
        k_prep<<<PREP_TOT, 256>>>(img, spkrec, t);
        k_stdp<<<gridS, 256>>>();
    }
    k_write_w<<<(N_SZ * IN_SZ + 255) / 256, 256>>>(outW);
}